// round 8
// baseline (speedup 1.0000x reference)
#include <cuda_runtime.h>
#include <math.h>

#define B_ 32
#define T_ 720
#define N_ 321

constexpr int L0C = 7395840;          // 32*720*321
constexpr int L1C = 3697927;          // (L0+15)//2
constexpr int L2C = 1848971;
constexpr int L3C = 924493;
constexpr long long KMED = (L1C - 1) / 2;

// padded (16B-aligned) buffer lengths
constexpr int L1P = 3697928;
constexpr int L2P = 1848972;
constexpr int L3P = 924496;

// per-chain: d1 | d2 | d3 | a3 | cmp
constexpr long long CH2 = (long long)L1P + L2P + 2LL * L3P + L1P;
constexpr size_t SCRATCH_SZ = (size_t)2 * L0C + 2 * CH2;

constexpr int NBLK = 3612;            // ceil(L1C/1024) == ceil(L0C/2048)

// sym8 filters -> FFMA immediates after unroll
__device__ constexpr float LO[16] = {
    -3.3824159510061256e-03f, -5.4213233179114810e-04f,  3.1695087811492980e-02f,
     7.6074873249176050e-03f, -1.4329423835080970e-01f, -6.1273359067658524e-02f,
     4.8135965125837220e-01f,  7.7718575170052350e-01f,  3.6444189483533895e-01f,
    -5.1945838107709040e-02f, -2.7219029917056003e-02f,  4.9137179673607506e-02f,
     3.8087520138906150e-03f, -1.4952258337048230e-02f, -3.0292051472136680e-04f,
     1.8899503327594609e-03f
};
__device__ constexpr float HI[16] = {
    -1.8899503327594609e-03f, -3.0292051472136680e-04f,  1.4952258337048230e-02f,
     3.8087520138906150e-03f, -4.9137179673607506e-02f, -2.7219029917056003e-02f,
     5.1945838107709040e-02f,  3.6444189483533895e-01f, -7.7718575170052350e-01f,
     4.8135965125837220e-01f,  6.1273359067658524e-02f, -1.4329423835080970e-01f,
    -7.6074873249176050e-03f,  3.1695087811492980e-02f,  5.4213233179114810e-04f,
    -3.3824159510061256e-03f
};

struct SelState {
    unsigned int prefix;
    unsigned long long k;
    float lam;
};

__device__ __align__(16) float g_scratch[SCRATCH_SZ];
__device__ unsigned int g_hist[2 * 4096];   // zero-init; re-zeroed by fused selects
__device__ unsigned int g_done[8];          // done-counters, self-resetting
__device__ unsigned int g_cnt[2];           // compact counters, self-resetting
__device__ SelState g_sel[2];

// ---------------------------------------------------------------------------
// fused last-block radix-select step (non-blocking last-block pattern)
// ---------------------------------------------------------------------------
__device__ __forceinline__ void block_select(unsigned int* __restrict__ hist,
                                             SelState* __restrict__ st, int pass,
                                             unsigned int* __restrict__ done,
                                             unsigned int nblocks,
                                             unsigned int* sbins,
                                             unsigned int* alsoReset) {
    __shared__ unsigned int lastFlag;
    __shared__ unsigned long long ps[256];
    int tid = threadIdx.x;
    if (tid == 0) {
        __threadfence();
        lastFlag = (atomicAdd(done, 1u) == nblocks - 1u) ? 1u : 0u;
    }
    __syncthreads();
    if (!lastFlag) return;

    unsigned long long s = 0;
    #pragma unroll
    for (int j = 0; j < 16; ++j) {
        unsigned int c = atomicExch(&hist[tid * 16 + j], 0u);
        sbins[tid * 16 + j] = c;
        s += c;
    }
    ps[tid] = s;
    __syncthreads();
    if (tid == 0) {
        long long k = (pass == 0) ? (long long)KMED : (long long)st->k;
        long long cum = 0;
        int chunk = 0;
        for (; chunk < 255; ++chunk) {
            if (cum + (long long)ps[chunk] > k) break;
            cum += (long long)ps[chunk];
        }
        int b = chunk * 16;
        for (;; ++b) {
            unsigned int c = sbins[b];
            if (cum + (long long)c > k) break;
            cum += c;
        }
        st->k = (unsigned long long)(k - cum);
        if (pass == 0) {
            st->prefix = (unsigned int)b;
        } else if (pass == 1) {
            st->prefix = (st->prefix << 12) | (unsigned int)b;
        } else {
            unsigned int u = (st->prefix << 8) | (unsigned int)b;
            float med = __uint_as_float(u);
            st->lam = (med / 0.6745f) * (float)sqrt(2.0 * log((double)L0C));
        }
        *done = 0u;
        if (alsoReset) *alsoReset = 0u;
    }
}

// ---------------------------------------------------------------------------
// moving average (K=25, edge-replicated) along T + residual  (R3 version)
// ---------------------------------------------------------------------------
#define MA_CH 48
#define MA_NCH (T_ / MA_CH)

__global__ __launch_bounds__(256)
void movavg_kernel(const float* __restrict__ x,
                   float* __restrict__ trend, float* __restrict__ res) {
    int tid = blockIdx.x * blockDim.x + threadIdx.x;
    int total = B_ * MA_NCH * N_;
    if (tid >= total) return;
    int n = tid % N_;
    int r = tid / N_;
    int ch = r % MA_NCH;
    int b = r / MA_NCH;

    const float* xb = x + (size_t)b * T_ * N_ + n;
    float* tb = trend + (size_t)b * T_ * N_ + n;
    float* rb = res + (size_t)b * T_ * N_ + n;

    int t0 = ch * MA_CH;
    float s = 0.f;
    #pragma unroll
    for (int j = -12; j <= 12; ++j) {
        int tt = t0 + j;
        tt = min(max(tt, 0), T_ - 1);
        s += __ldg(xb + (size_t)tt * N_);
    }
    for (int t = t0; t < t0 + MA_CH; ++t) {
        float tr = s / 25.0f;
        float xc = __ldg(xb + (size_t)t * N_);
        tb[(size_t)t * N_] = tr;
        rb[(size_t)t * N_] = xc - tr;
        int tl = max(t - 12, 0);
        int th = min(t + 13, T_ - 1);
        s += __ldg(xb + (size_t)th * N_) - __ldg(xb + (size_t)tl * N_);
    }
}

// ---------------------------------------------------------------------------
// fused 3-level forward DWT + pass-0 histogram + fused select.
// Block bx: d1[1024bx..+1023], d2[512bx..+511], d3/a3[256bx..+255].
// a1/a2 tiles live in even/odd-deinterleaved smem.
// ---------------------------------------------------------------------------
#define SIGN_ 2160      // sig tile words, SIGLO = 2048bx-112
#define A1N_ 1072       // a1 tile, A1LO = 1024bx-48
#define A2N_ 528        // a2 tile, M2LO = 512bx-16

__global__ __launch_bounds__(256)
void dwt_fused_kernel(const float* __restrict__ sigbase, long long sstr,
                      float* __restrict__ d1b, float* __restrict__ d2b,
                      float* __restrict__ d3b, float* __restrict__ a3b,
                      unsigned int* __restrict__ histb,
                      SelState* __restrict__ selb,
                      unsigned int* __restrict__ doneb) {
    __shared__ float sE[1080], sO[1080];
    __shared__ float a1E[536], a1O[536];
    __shared__ float a2E[264], a2O[264];
    __shared__ unsigned int hist_s[4096];

    int tid = threadIdx.x;
    int bx = blockIdx.x, chain = blockIdx.y;
    bool eblk = (bx == 0) || (bx == NBLK - 1);
    const float* sig = sigbase + (size_t)chain * sstr;
    float* d1 = d1b + (size_t)chain * CH2;
    float* d2 = d2b + (size_t)chain * CH2;
    float* d3 = d3b + (size_t)chain * CH2;
    float* a3 = a3b + (size_t)chain * CH2;

    for (int i = tid; i < 4096; i += 256) hist_s[i] = 0u;

    // ---- load sig tile (deinterleaved) ----
    int SIGLO = 2048 * bx - 112;
    if (!eblk) {
        const float4* p = reinterpret_cast<const float4*>(sig + SIGLO);
        for (int i4 = tid; i4 < SIGN_ / 4; i4 += 256) {
            float4 v = __ldg(p + i4);
            int k = 2 * i4;
            sE[k] = v.x; sO[k] = v.y; sE[k + 1] = v.z; sO[k + 1] = v.w;
        }
    } else {
        for (int w = tid; w < SIGN_; w += 256) {
            int g = SIGLO + w;
            if (g < 0) g = -1 - g;
            else if (g >= L0C) g = 2 * L0C - 1 - g;
            float v = __ldg(sig + g);
            if (w & 1) sO[w >> 1] = v; else sE[w >> 1] = v;
        }
    }
    __syncthreads();

    // ---- level 1: a1[m] = sum_u sO[m+8-u]*LO[2u] + sE[m+8-u]*LO[2u+1] ----
    int A1LO = 1024 * bx - 48;
    #pragma unroll
    for (int half = 0; half < 2; ++half) {
        int m0;
        if (half == 0) m0 = 4 * tid;
        else { if (tid >= 12) break; m0 = 1024 + 4 * tid; }
        float O[12], E[12];
        #pragma unroll
        for (int q = 0; q < 3; ++q) {
            float4 vo = *reinterpret_cast<const float4*>(&sO[m0 + 4 * q]);
            O[4*q] = vo.x; O[4*q+1] = vo.y; O[4*q+2] = vo.z; O[4*q+3] = vo.w;
            float4 ve = *reinterpret_cast<const float4*>(&sE[m0 + 4 * q]);
            E[4*q] = ve.x; E[4*q+1] = ve.y; E[4*q+2] = ve.z; E[4*q+3] = ve.w;
        }
        float A[4], D[4];
        #pragma unroll
        for (int c = 0; c < 4; ++c) {
            float sa = 0.f, sd = 0.f;
            #pragma unroll
            for (int u = 0; u < 8; ++u) {
                float vo = O[c + 8 - u], ve = E[c + 8 - u];
                sa = fmaf(vo, LO[2*u], sa); sa = fmaf(ve, LO[2*u+1], sa);
                sd = fmaf(vo, HI[2*u], sd); sd = fmaf(ve, HI[2*u+1], sd);
            }
            A[c] = sa; D[c] = sd;
        }
        int h = m0 >> 1;
        a1E[h] = A[0]; a1O[h] = A[1]; a1E[h+1] = A[2]; a1O[h+1] = A[3];
        if (m0 >= 48) {
            int j1 = A1LO + m0;
            if (j1 + 4 <= L1C) {
                *reinterpret_cast<float4*>(d1 + j1) = make_float4(D[0], D[1], D[2], D[3]);
                #pragma unroll
                for (int c = 0; c < 4; ++c)
                    atomicAdd(&hist_s[__float_as_uint(fabsf(D[c])) >> 20], 1u);
            } else {
                for (int c = 0; c < 4 && j1 + c < L1C; ++c) {
                    d1[j1 + c] = D[c];
                    atomicAdd(&hist_s[__float_as_uint(fabsf(D[c])) >> 20], 1u);
                }
            }
        }
    }
    __syncthreads();

    // ---- level 2: a2[n] from a1 parity tiles ----
    int M2LO = 512 * bx - 16;
    if (!eblk) {
        {
            int n0 = 2 * tid;
            float O[10], E[10];
            #pragma unroll
            for (int q = 0; q < 10; ++q) { O[q] = a1O[n0 + q]; E[q] = a1E[n0 + q]; }
            float A2v[2], D2v[2];
            #pragma unroll
            for (int c = 0; c < 2; ++c) {
                float sa = 0.f, sd = 0.f;
                #pragma unroll
                for (int u = 0; u < 8; ++u) {
                    float vo = O[c + 8 - u], ve = E[c + 8 - u];
                    sa = fmaf(vo, LO[2*u], sa); sa = fmaf(ve, LO[2*u+1], sa);
                    sd = fmaf(vo, HI[2*u], sd); sd = fmaf(ve, HI[2*u+1], sd);
                }
                A2v[c] = sa; D2v[c] = sd;
            }
            a2E[tid] = A2v[0]; a2O[tid] = A2v[1];
            if (tid >= 8) {
                int j2 = M2LO + n0;
                *reinterpret_cast<float2*>(d2 + j2) = make_float2(D2v[0], D2v[1]);
            }
        }
        if (tid < 16) {
            int n = 512 + tid;
            float sa = 0.f, sd = 0.f;
            #pragma unroll
            for (int u = 0; u < 8; ++u) {
                float vo = a1O[n + 8 - u], ve = a1E[n + 8 - u];
                sa = fmaf(vo, LO[2*u], sa); sa = fmaf(ve, LO[2*u+1], sa);
                sd = fmaf(vo, HI[2*u], sd); sd = fmaf(ve, HI[2*u+1], sd);
            }
            if (n & 1) a2O[n >> 1] = sa; else a2E[n >> 1] = sa;
            d2[M2LO + n] = sd;
        }
    } else {
        for (int pass = 0; pass < 3; ++pass) {
            int n;
            if (pass < 2) n = 2 * tid + pass;
            else { if (tid >= 16) break; n = 512 + tid; }
            int j2 = M2LO + n;
            float sa = 0.f, sd = 0.f;
            if (j2 >= 0 && j2 < L2C) {
                #pragma unroll
                for (int t = 0; t < 16; ++t) {
                    int s = 2 * j2 + 1 - t;
                    if (s < 0) s = -1 - s;
                    else if (s >= L1C) s = 2 * L1C - 1 - s;
                    int m = s - A1LO;
                    float v = (m & 1) ? a1O[m >> 1] : a1E[m >> 1];
                    sa = fmaf(v, LO[t], sa);
                    sd = fmaf(v, HI[t], sd);
                }
                if (n >= 16) d2[j2] = sd;
            }
            if (n & 1) a2O[n >> 1] = sa; else a2E[n >> 1] = sa;
        }
    }
    __syncthreads();

    // ---- level 3 ----
    int j3 = 256 * bx + tid;
    if (!eblk) {
        float sa = 0.f, sd = 0.f;
        #pragma unroll
        for (int u = 0; u < 8; ++u) {
            float vo = a2O[tid + 8 - u], ve = a2E[tid + 8 - u];
            sa = fmaf(vo, LO[2*u], sa); sa = fmaf(ve, LO[2*u+1], sa);
            sd = fmaf(vo, HI[2*u], sd); sd = fmaf(ve, HI[2*u+1], sd);
        }
        a3[j3] = sa; d3[j3] = sd;
    } else if (j3 < L3C) {
        float sa = 0.f, sd = 0.f;
        #pragma unroll
        for (int t = 0; t < 16; ++t) {
            int s = 2 * j3 + 1 - t;
            if (s < 0) s = -1 - s;
            else if (s >= L2C) s = 2 * L2C - 1 - s;
            int p = s - M2LO;
            float v = (p & 1) ? a2O[p >> 1] : a2E[p >> 1];
            sa = fmaf(v, LO[t], sa);
            sd = fmaf(v, HI[t], sd);
        }
        a3[j3] = sa; d3[j3] = sd;
    }
    __syncthreads();

    // ---- flush pass-0 histogram + fused select ----
    unsigned int* h = histb + chain * 4096;
    for (int i = tid; i < 4096; i += 256) {
        unsigned int c = hist_s[i];
        if (c) atomicAdd(&h[i], c);
    }
    __syncthreads();
    block_select(h, selb + chain, 0, doneb + chain * 4 + 0, gridDim.x, hist_s, nullptr);
}

// ---------------------------------------------------------------------------
// pass 1 over d1: 12-bit mid histogram + compact matching elements
// ---------------------------------------------------------------------------
__global__ __launch_bounds__(256)
void histP1_kernel(const float* __restrict__ d1b,
                   unsigned int* __restrict__ histb,
                   SelState* __restrict__ selb, unsigned int* __restrict__ doneb,
                   unsigned int* __restrict__ cmpb, unsigned int* __restrict__ cntb) {
    int chain = blockIdx.y;
    const float* d = d1b + (size_t)chain * CH2;
    unsigned int* hist = histb + chain * 4096;
    unsigned int* cmp = cmpb + (size_t)chain * CH2;   // cmp area is last L1P of chunk; offset applied by caller
    unsigned int* cnt = cntb + chain;
    unsigned int pfx = selb[chain].prefix;
    __shared__ unsigned int sh[4096];
    for (int i = threadIdx.x; i < 4096; i += 256) sh[i] = 0u;
    __syncthreads();

    int lane = threadIdx.x & 31;
    int nvec = L1C >> 2;
    int stride = gridDim.x * blockDim.x;
    const float4* dv = reinterpret_cast<const float4*>(d);
    for (int i = blockIdx.x * blockDim.x + threadIdx.x; i < nvec; i += stride) {
        float4 v = __ldg(dv + i);
        float vv[4] = {v.x, v.y, v.z, v.w};
        #pragma unroll
        for (int q = 0; q < 4; ++q) {
            unsigned int u = __float_as_uint(fabsf(vv[q]));
            bool match = (u >> 20) == pfx;
            if (match) atomicAdd(&sh[(u >> 8) & 0xFFFu], 1u);
            unsigned int amask = __activemask();
            unsigned int mask = __ballot_sync(amask, match);
            if (match) {
                unsigned int leader = __ffs(mask) - 1u;
                unsigned int rank = __popc(mask & ((1u << lane) - 1u));
                unsigned int base = 0;
                if ((unsigned)lane == leader) base = atomicAdd(cnt, (unsigned)__popc(mask));
                base = __shfl_sync(mask, base, leader);
                cmp[base + rank] = u;
            }
        }
    }
    if (blockIdx.x == 0 && threadIdx.x < (L1C & 3)) {
        unsigned int u = __float_as_uint(fabsf(__ldg(d + (nvec << 2) + threadIdx.x)));
        if ((u >> 20) == pfx) {
            atomicAdd(&sh[(u >> 8) & 0xFFFu], 1u);
            unsigned int base = atomicAdd(cnt, 1u);
            cmp[base] = u;
        }
    }
    __syncthreads();
    for (int i = threadIdx.x; i < 4096; i += 256) {
        unsigned int c = sh[i];
        if (c) atomicAdd(&hist[i], c);
    }
    __syncthreads();
    block_select(hist, selb + chain, 1, doneb + chain * 4 + 1, gridDim.x, sh, nullptr);
}

// ---------------------------------------------------------------------------
// pass 2 over compact buffer (tiny)
// ---------------------------------------------------------------------------
__global__ __launch_bounds__(256)
void histP2_kernel(const unsigned int* __restrict__ cmpb,
                   unsigned int* __restrict__ cntb,
                   unsigned int* __restrict__ histb,
                   SelState* __restrict__ selb, unsigned int* __restrict__ doneb) {
    int chain = blockIdx.y;
    const unsigned int* cmp = cmpb + (size_t)chain * CH2;
    unsigned int* hist = histb + chain * 4096;
    unsigned int n = cntb[chain];
    unsigned int pfx = selb[chain].prefix;   // 24-bit
    __shared__ unsigned int sh[4096];
    for (int i = threadIdx.x; i < 4096; i += 256) sh[i] = 0u;
    __syncthreads();

    int stride = gridDim.x * blockDim.x;
    for (unsigned int i = blockIdx.x * blockDim.x + threadIdx.x; i < n; i += stride) {
        unsigned int u = cmp[i];
        if ((u >> 8) == pfx) atomicAdd(&sh[u & 0xFFu], 1u);
    }
    __syncthreads();
    for (int i = threadIdx.x; i < 256; i += 256) {
        unsigned int c = sh[i];
        if (c) atomicAdd(&hist[i], c);
    }
    __syncthreads();
    block_select(hist, selb + chain, 2, doneb + chain * 4 + 2, gridDim.x, sh,
                 cntb + chain);
}

// ---------------------------------------------------------------------------
// fused 3-level inverse DWT with thresholding + final 4-way output
// ---------------------------------------------------------------------------
__device__ __forceinline__ float thrf(float d, float lam, float alam) {
    float ad = fabsf(d);
    return (ad >= lam) ? copysignf(ad - alam, d) : 0.0f;
}

__global__ __launch_bounds__(256)
void idwt_fused_kernel(const float* __restrict__ a3b, const float* __restrict__ d3b,
                       const float* __restrict__ d2b, const float* __restrict__ d1b,
                       const float* __restrict__ sigbase, long long sstr,
                       float* __restrict__ out, const SelState* __restrict__ sel) {
    __shared__ float A3s[272], D3s[272];
    __shared__ __align__(16) float R2s[524];
    __shared__ __align__(16) float R1s[1032];

    int tid = threadIdx.x;
    int bx = blockIdx.x, chain = blockIdx.y;
    const float* a3 = a3b + (size_t)chain * CH2;
    const float* d3 = d3b + (size_t)chain * CH2;
    const float* d2 = d2b + (size_t)chain * CH2;
    const float* d1 = d1b + (size_t)chain * CH2;
    const float* sig = sigbase + (size_t)chain * sstr;
    float* out_diff = out + (size_t)(2 * chain) * L0C;
    float* out_nn   = out + (size_t)(2 * chain + 1) * L0C;
    float lam = sel[chain].lam, alam = 0.85f * lam;

    // phase 0: a3/d3 tile (d3 thresholded)
    int Q0 = 256 * bx;
    for (int w = tid; w < 269; w += 256) {
        int q = Q0 + w;
        bool ok = q < L3C;
        A3s[w] = ok ? __ldg(a3 + q) : 0.f;
        D3s[w] = ok ? thrf(__ldg(d3 + q), lam, alam) : 0.f;
    }
    __syncthreads();

    // phase 1: r2 tile
    int P0 = 512 * bx;
    for (int e = tid; e < 523; e += 256) {
        int p = P0 + e;
        float v = 0.f;
        if (p < L2C) {
            int tb = (e & 1) ? 0 : 1;
            int h = e >> 1;
            #pragma unroll
            for (int r = 0; r < 8; ++r) {
                v = fmaf(A3s[h + r], LO[2*r + tb], v);
                v = fmaf(D3s[h + r], HI[2*r + tb], v);
            }
        }
        R2s[e] = v;
    }
    __syncthreads();

    // phase 2: r1 tile (reads d2 global, thresholded)
    int I0 = 1024 * bx;
    for (int f = tid; f < 1031; f += 256) {
        int i = I0 + f;
        float v = 0.f;
        if (i < L1C) {
            int tb = (f & 1) ? 0 : 1;
            int h = f >> 1;
            int gd = i >> 1;
            #pragma unroll
            for (int r = 0; r < 8; ++r) {
                float dv = thrf(__ldg(d2 + gd + r), lam, alam);
                v = fmaf(R2s[h + r], LO[2*r + tb], v);
                v = fmaf(dv, HI[2*r + tb], v);
            }
        }
        R1s[f] = v;
    }
    __syncthreads();

    // phase 3: final 8 outputs per thread (reads d1 + sig global)
    int k0 = 2048 * bx + 8 * tid;
    if (k0 < L0C) {
        int f0 = 4 * tid;
        float R[12], DD[12];
        #pragma unroll
        for (int q = 0; q < 3; ++q) {
            float4 vr = *reinterpret_cast<const float4*>(&R1s[f0 + 4 * q]);
            R[4*q] = vr.x; R[4*q+1] = vr.y; R[4*q+2] = vr.z; R[4*q+3] = vr.w;
            float4 vd = __ldg(reinterpret_cast<const float4*>(d1 + (k0 >> 1) + 4 * q));
            DD[4*q]   = thrf(vd.x, lam, alam);
            DD[4*q+1] = thrf(vd.y, lam, alam);
            DD[4*q+2] = thrf(vd.z, lam, alam);
            DD[4*q+3] = thrf(vd.w, lam, alam);
        }
        float o[8];
        #pragma unroll
        for (int c = 0; c < 8; ++c) {
            int base = c >> 1;
            int tb = (c & 1) ? 0 : 1;
            float v = 0.f;
            #pragma unroll
            for (int r = 0; r < 8; ++r) {
                v = fmaf(R[base + r], LO[2*r + tb], v);
                v = fmaf(DD[base + r], HI[2*r + tb], v);
            }
            o[c] = v;
        }
        #pragma unroll
        for (int q = 0; q < 2; ++q) {
            float4 s = __ldg(reinterpret_cast<const float4*>(sig + k0 + 4 * q));
            *reinterpret_cast<float4*>(out_nn + k0 + 4 * q) =
                make_float4(o[4*q], o[4*q+1], o[4*q+2], o[4*q+3]);
            *reinterpret_cast<float4*>(out_diff + k0 + 4 * q) =
                make_float4(s.x - o[4*q], s.y - o[4*q+1], s.z - o[4*q+2], s.w - o[4*q+3]);
        }
    }
}

// ---------------------------------------------------------------------------
static inline int gridFor(long long n, int per) { return (int)((n + per - 1) / per); }

extern "C" void kernel_launch(void* const* d_in, const int* in_sizes, int n_in,
                              void* d_out, int out_size) {
    const float* x = (const float*)d_in[0];
    float* out = (float*)d_out;

    float* scr = nullptr;
    unsigned int* hist = nullptr;
    unsigned int* done = nullptr;
    unsigned int* cnt = nullptr;
    SelState* sel = nullptr;
    cudaGetSymbolAddress((void**)&scr, g_scratch);
    cudaGetSymbolAddress((void**)&hist, g_hist);
    cudaGetSymbolAddress((void**)&done, g_done);
    cudaGetSymbolAddress((void**)&cnt, g_cnt);
    cudaGetSymbolAddress((void**)&sel, g_sel);

    float* trend = scr;                       // sig stride = L0C
    float* base2 = scr + (size_t)2 * L0C;     // chain stride = CH2
    float* d1 = base2;
    float* d2 = base2 + L1P;
    float* d3 = d2 + L2P;
    float* a3 = d3 + L3P;
    unsigned int* cmp = reinterpret_cast<unsigned int*>(a3 + L3P);

    movavg_kernel<<<gridFor((long long)B_ * MA_NCH * N_, 256), 256>>>(x, trend, scr + L0C);

    dwt_fused_kernel<<<dim3(NBLK, 2), 256>>>(trend, L0C, d1, d2, d3, a3, hist, sel, done);

    const int HB = 592;
    histP1_kernel<<<dim3(HB, 2), 256>>>(d1, hist, sel, done, cmp, cnt);
    histP2_kernel<<<dim3(60, 2), 256>>>(cmp, cnt, hist, sel, done);

    idwt_fused_kernel<<<dim3(NBLK, 2), 256>>>(a3, d3, d2, d1, trend, L0C, out, sel);

    (void)in_sizes; (void)n_in; (void)out_size;
}

// round 9
// speedup vs baseline: 1.7501x; 1.7501x over previous
#include <cuda_runtime.h>
#include <math.h>

#define B_ 32
#define T_ 720
#define N_ 321

constexpr int L0C = 7395840;          // 32*720*321
constexpr int L1C = 3697927;          // (L0+15)//2
constexpr int L2C = 1848971;
constexpr int L3C = 924493;
constexpr int R2C = 2 * L3C - 14;     // 1848972
constexpr int R1C = 2 * L2C - 14;     // 3697928
constexpr long long KMED = (L1C - 1) / 2;

// padded (16B-aligned) buffer lengths
constexpr int L1P = 3697928;
constexpr int L2P = 1848972;
constexpr int L3P = 924496;

constexpr long long CHAIN = 2LL * L1P + 2LL * L2P + 2LL * L3P + R2C + R1C;
constexpr size_t SCRATCH_SZ = (size_t)2 * L0C + 2 * CHAIN;

// sym8 filters -> FFMA immediates after unroll
__device__ constexpr float LO[16] = {
    -3.3824159510061256e-03f, -5.4213233179114810e-04f,  3.1695087811492980e-02f,
     7.6074873249176050e-03f, -1.4329423835080970e-01f, -6.1273359067658524e-02f,
     4.8135965125837220e-01f,  7.7718575170052350e-01f,  3.6444189483533895e-01f,
    -5.1945838107709040e-02f, -2.7219029917056003e-02f,  4.9137179673607506e-02f,
     3.8087520138906150e-03f, -1.4952258337048230e-02f, -3.0292051472136680e-04f,
     1.8899503327594609e-03f
};
__device__ constexpr float HI[16] = {
    -1.8899503327594609e-03f, -3.0292051472136680e-04f,  1.4952258337048230e-02f,
     3.8087520138906150e-03f, -4.9137179673607506e-02f, -2.7219029917056003e-02f,
     5.1945838107709040e-02f,  3.6444189483533895e-01f, -7.7718575170052350e-01f,
     4.8135965125837220e-01f,  6.1273359067658524e-02f, -1.4329423835080970e-01f,
    -7.6074873249176050e-03f,  3.1695087811492980e-02f,  5.4213233179114810e-04f,
    -3.3824159510061256e-03f
};

struct SelState {
    unsigned int prefix;
    unsigned long long k;
    float lam;
};

__device__ __align__(16) float g_scratch[SCRATCH_SZ];
__device__ unsigned int g_hist[2 * 4096];   // zero-init; re-zeroed by fused selects
__device__ unsigned int g_done[8];          // done-counters, self-resetting
__device__ SelState g_sel[2];

// ---------------------------------------------------------------------------
// fused last-block radix-select (non-blocking; only last hist block selects)
// ---------------------------------------------------------------------------
__device__ __forceinline__ void block_select(unsigned int* __restrict__ hist,
                                             SelState* __restrict__ st, int pass,
                                             unsigned int* __restrict__ done,
                                             unsigned int nblocks,
                                             unsigned int* sbins) {
    __shared__ unsigned int lastFlag;
    __shared__ unsigned long long ps[256];
    int tid = threadIdx.x;
    if (tid == 0) {
        __threadfence();
        lastFlag = (atomicAdd(done, 1u) == nblocks - 1u) ? 1u : 0u;
    }
    __syncthreads();
    if (!lastFlag) return;

    unsigned long long s = 0;
    #pragma unroll
    for (int j = 0; j < 16; ++j) {
        unsigned int c = atomicExch(&hist[tid * 16 + j], 0u);
        sbins[tid * 16 + j] = c;
        s += c;
    }
    ps[tid] = s;
    __syncthreads();
    if (tid == 0) {
        long long k = (pass == 0) ? (long long)KMED : (long long)st->k;
        long long cum = 0;
        int chunk = 0;
        for (; chunk < 255; ++chunk) {
            if (cum + (long long)ps[chunk] > k) break;
            cum += (long long)ps[chunk];
        }
        int b = chunk * 16;
        for (;; ++b) {
            unsigned int c = sbins[b];
            if (cum + (long long)c > k) break;
            cum += c;
        }
        st->k = (unsigned long long)(k - cum);
        if (pass == 0) {
            st->prefix = (unsigned int)b;
        } else if (pass == 1) {
            st->prefix = (st->prefix << 12) | (unsigned int)b;
        } else {
            unsigned int u = (st->prefix << 8) | (unsigned int)b;
            float med = __uint_as_float(u);
            st->lam = (med / 0.6745f) * (float)sqrt(2.0 * log((double)L0C));
        }
        *done = 0u;   // reset for next graph replay
    }
}

// ---------------------------------------------------------------------------
// moving average (K=25, edge-replicated) along T + residual  (R3 version)
// ---------------------------------------------------------------------------
#define MA_CH 48
#define MA_NCH (T_ / MA_CH)

__global__ __launch_bounds__(256)
void movavg_kernel(const float* __restrict__ x,
                   float* __restrict__ trend, float* __restrict__ res) {
    int tid = blockIdx.x * blockDim.x + threadIdx.x;
    int total = B_ * MA_NCH * N_;
    if (tid >= total) return;
    int n = tid % N_;
    int r = tid / N_;
    int ch = r % MA_NCH;
    int b = r / MA_NCH;

    const float* xb = x + (size_t)b * T_ * N_ + n;
    float* tb = trend + (size_t)b * T_ * N_ + n;
    float* rb = res + (size_t)b * T_ * N_ + n;

    int t0 = ch * MA_CH;
    float s = 0.f;
    #pragma unroll
    for (int j = -12; j <= 12; ++j) {
        int tt = t0 + j;
        tt = min(max(tt, 0), T_ - 1);
        s += __ldg(xb + (size_t)tt * N_);
    }
    for (int t = t0; t < t0 + MA_CH; ++t) {
        float tr = s / 25.0f;
        float xc = __ldg(xb + (size_t)t * N_);
        tb[(size_t)t * N_] = tr;
        rb[(size_t)t * N_] = xc - tr;
        int tl = max(t - 12, 0);
        int th = min(t + 13, T_ - 1);
        s += __ldg(xb + (size_t)th * N_) - __ldg(xb + (size_t)tl * N_);
    }
}

// ---------------------------------------------------------------------------
// forward DWT core, 4 output-pairs per thread (R3)
// ---------------------------------------------------------------------------
__device__ __forceinline__ void dwt_compute4(const float* __restrict__ a, int L,
                                             int tid, float accA[4], float accD[4]) {
    float w[24];
    int s0 = 8 * tid - 16;
    if (s0 >= 0 && s0 + 24 <= L) {
        const float4* p = reinterpret_cast<const float4*>(a + s0);
        #pragma unroll
        for (int q = 0; q < 6; ++q) {
            float4 v = __ldg(p + q);
            w[4*q+0] = v.x; w[4*q+1] = v.y; w[4*q+2] = v.z; w[4*q+3] = v.w;
        }
    } else {
        #pragma unroll
        for (int q = 0; q < 24; ++q) {
            int s = s0 + q;
            if (s < 0) s = -1 - s;
            else if (s >= L) s = 2 * L - 1 - s;
            w[q] = __ldg(a + s);
        }
    }
    #pragma unroll
    for (int c = 0; c < 4; ++c) {
        float sa = 0.f, sd = 0.f;
        #pragma unroll
        for (int t = 0; t < 16; ++t) {
            float v = w[2*c + 17 - t];
            sa = fmaf(v, LO[t], sa);
            sd = fmaf(v, HI[t], sd);
        }
        accA[c] = sa; accD[c] = sd;
    }
}

__device__ __forceinline__ void dwt_store4(float* __restrict__ ca, float* __restrict__ cd,
                                           int j0, int Lc, const float accA[4],
                                           const float accD[4]) {
    if (j0 + 4 <= Lc) {
        *reinterpret_cast<float4*>(ca + j0) = make_float4(accA[0], accA[1], accA[2], accA[3]);
        *reinterpret_cast<float4*>(cd + j0) = make_float4(accD[0], accD[1], accD[2], accD[3]);
    } else {
        for (int c = 0; c < 4 && j0 + c < Lc; ++c) { ca[j0+c] = accA[c]; cd[j0+c] = accD[c]; }
    }
}

// level-1 dwt with fused pass-0 histogram + fused last-block select (R7-proven)
__global__ __launch_bounds__(256)
void dwt4_hist_kernel(const float* __restrict__ abase, long long astr, int L,
                      float* __restrict__ cabase, float* __restrict__ cdbase,
                      long long cstr, int Lc, unsigned int* __restrict__ histb,
                      SelState* __restrict__ selb, unsigned int* __restrict__ doneb) {
    __shared__ unsigned int sh[4096];
    for (int i = threadIdx.x; i < 4096; i += 256) sh[i] = 0u;
    __syncthreads();

    int chain = blockIdx.y;
    int tid = blockIdx.x * blockDim.x + threadIdx.x;
    int j0 = 4 * tid;
    if (j0 < Lc) {
        const float* a = abase + (size_t)chain * astr;
        float* ca = cabase + (size_t)chain * cstr;
        float* cd = cdbase + (size_t)chain * cstr;
        float accA[4], accD[4];
        dwt_compute4(a, L, tid, accA, accD);
        dwt_store4(ca, cd, j0, Lc, accA, accD);
        int lim = min(4, Lc - j0);
        #pragma unroll
        for (int c = 0; c < 4; ++c)
            if (c < lim)
                atomicAdd(&sh[__float_as_uint(fabsf(accD[c])) >> 20], 1u);
    }
    __syncthreads();
    unsigned int* h = histb + chain * 4096;
    for (int i = threadIdx.x; i < 4096; i += 256) {
        unsigned int c = sh[i];
        if (c) atomicAdd(&h[i], c);
    }
    __syncthreads();
    block_select(h, selb + chain, 0, doneb + chain * 4 + 0, gridDim.x, sh);
}

// ---------------------------------------------------------------------------
// hist pass body (grid-stride over a block range) + fused select
// ---------------------------------------------------------------------------
__device__ __forceinline__ void hist_pass_body(const float* __restrict__ d, int len,
                                               unsigned int* __restrict__ hist,
                                               SelState* __restrict__ st,
                                               unsigned int* __restrict__ done,
                                               int pass, int bxx, int nb,
                                               unsigned int* sh) {
    for (int i = threadIdx.x; i < 4096; i += 256) sh[i] = 0u;
    __syncthreads();

    unsigned int pfx = st->prefix;
    int nvec = len >> 2;
    int stride = nb * 256;
    const float4* dv = reinterpret_cast<const float4*>(d);
    for (int i = bxx * 256 + threadIdx.x; i < nvec; i += stride) {
        float4 v = __ldg(dv + i);
        float vv[4] = {v.x, v.y, v.z, v.w};
        #pragma unroll
        for (int q = 0; q < 4; ++q) {
            unsigned int u = __float_as_uint(fabsf(vv[q]));
            if (pass == 1) { if ((u >> 20) == pfx) atomicAdd(&sh[(u >> 8) & 0xFFFu], 1u); }
            else           { if ((u >> 8)  == pfx) atomicAdd(&sh[u & 0xFFu], 1u); }
        }
    }
    if (bxx == 0 && threadIdx.x < (len & 3)) {
        unsigned int u = __float_as_uint(fabsf(__ldg(d + (nvec << 2) + threadIdx.x)));
        if (pass == 1) { if ((u >> 20) == pfx) atomicAdd(&sh[(u >> 8) & 0xFFFu], 1u); }
        else           { if ((u >> 8)  == pfx) atomicAdd(&sh[u & 0xFFu], 1u); }
    }
    __syncthreads();
    for (int i = threadIdx.x; i < 4096; i += 256) {
        unsigned int c = sh[i];
        if (c) atomicAdd(&hist[i], c);
    }
    __syncthreads();
    block_select(hist, st, pass, done, (unsigned)nb, sh);
}

// ---------------------------------------------------------------------------
// K2: blocks [0,gDwt) = dwt level 2; blocks [gDwt, gridDim.x) = hist pass 1
// ---------------------------------------------------------------------------
__global__ __launch_bounds__(256)
void k2_kernel(const float* __restrict__ a1b, float* __restrict__ a2b,
               float* __restrict__ d2b, const float* __restrict__ d1b,
               unsigned int* __restrict__ histb, SelState* __restrict__ selb,
               unsigned int* __restrict__ doneb, int gDwt) {
    __shared__ unsigned int sh[4096];
    int chain = blockIdx.y;
    if ((int)blockIdx.x < gDwt) {
        const float* a1 = a1b + (size_t)chain * CHAIN;
        float* a2 = a2b + (size_t)chain * CHAIN;
        float* d2 = d2b + (size_t)chain * CHAIN;
        int tid = blockIdx.x * 256 + threadIdx.x;
        int j0 = 4 * tid;
        if (j0 >= L2C) return;
        float accA[4], accD[4];
        dwt_compute4(a1, L1C, tid, accA, accD);
        dwt_store4(a2, d2, j0, L2C, accA, accD);
    } else {
        const float* d1 = d1b + (size_t)chain * CHAIN;
        hist_pass_body(d1, L1C, histb + chain * 4096, selb + chain,
                       doneb + chain * 4 + 1, 1,
                       blockIdx.x - gDwt, gridDim.x - gDwt, sh);
    }
}

// ---------------------------------------------------------------------------
// K3: blocks [0,gDwt) = dwt level 3; blocks [gDwt, gridDim.x) = hist pass 2
// ---------------------------------------------------------------------------
__global__ __launch_bounds__(256)
void k3_kernel(const float* __restrict__ a2b, float* __restrict__ a3b,
               float* __restrict__ d3b, const float* __restrict__ d1b,
               unsigned int* __restrict__ histb, SelState* __restrict__ selb,
               unsigned int* __restrict__ doneb, int gDwt) {
    __shared__ unsigned int sh[4096];
    int chain = blockIdx.y;
    if ((int)blockIdx.x < gDwt) {
        const float* a2 = a2b + (size_t)chain * CHAIN;
        float* a3 = a3b + (size_t)chain * CHAIN;
        float* d3 = d3b + (size_t)chain * CHAIN;
        int tid = blockIdx.x * 256 + threadIdx.x;
        int j0 = 4 * tid;
        if (j0 >= L3C) return;
        float accA[4], accD[4];
        dwt_compute4(a2, L2C, tid, accA, accD);
        dwt_store4(a3, d3, j0, L3C, accA, accD);
    } else {
        const float* d1 = d1b + (size_t)chain * CHAIN;
        hist_pass_body(d1, L1C, histb + chain * 4096, selb + chain,
                       doneb + chain * 4 + 2, 2,
                       blockIdx.x - gDwt, gridDim.x - gDwt, sh);
    }
}

// ---------------------------------------------------------------------------
// inverse DWT with fused thresholding, 8 outputs/thread (R3)
// ---------------------------------------------------------------------------
__device__ __forceinline__ float thrf(float d, float lam, float alam) {
    float ad = fabsf(d);
    return (ad >= lam) ? copysignf(ad - alam, d) : 0.0f;
}

__device__ __forceinline__ void idwt_compute8(const float* __restrict__ ca,
                                              const float* __restrict__ cd,
                                              int Lc, int t, float lam, float alam,
                                              float o[8]) {
    int i0 = 4 * t;
    float A[12], D[12];
    if (i0 + 12 <= Lc) {
        const float4* pa = reinterpret_cast<const float4*>(ca + i0);
        const float4* pd = reinterpret_cast<const float4*>(cd + i0);
        #pragma unroll
        for (int q = 0; q < 3; ++q) {
            float4 va = __ldg(pa + q);
            A[4*q+0] = va.x; A[4*q+1] = va.y; A[4*q+2] = va.z; A[4*q+3] = va.w;
            float4 vd = __ldg(pd + q);
            D[4*q+0] = thrf(vd.x, lam, alam); D[4*q+1] = thrf(vd.y, lam, alam);
            D[4*q+2] = thrf(vd.z, lam, alam); D[4*q+3] = thrf(vd.w, lam, alam);
        }
    } else {
        #pragma unroll
        for (int q = 0; q < 12; ++q) {
            int i = i0 + q;
            bool ok = i < Lc;
            A[q] = ok ? __ldg(ca + i) : 0.f;
            D[q] = ok ? thrf(__ldg(cd + i), lam, alam) : 0.f;
        }
    }
    #pragma unroll
    for (int c = 0; c < 8; ++c) {
        int base = c >> 1;
        int tb = (c & 1) ? 0 : 1;
        float v = 0.f;
        #pragma unroll
        for (int r = 0; r < 8; ++r) {
            v = fmaf(A[base + r], LO[2*r + tb], v);
            v = fmaf(D[base + r], HI[2*r + tb], v);
        }
        o[c] = v;
    }
}

__global__ __launch_bounds__(256)
void idwt8_kernel(const float* __restrict__ cabase, const float* __restrict__ cdbase,
                  long long str, int Lc, float* __restrict__ outbase, long long ostr,
                  const SelState* __restrict__ sel) {
    int chain = blockIdx.y;
    const float* ca = cabase + (size_t)chain * str;
    const float* cd = cdbase + (size_t)chain * str;
    float* out = outbase + (size_t)chain * ostr;
    int t = blockIdx.x * blockDim.x + threadIdx.x;
    int Lout = 2 * Lc - 14;
    int k0 = 8 * t;
    if (k0 >= Lout) return;
    float lam = sel[chain].lam, alam = 0.85f * lam;
    float o[8];
    idwt_compute8(ca, cd, Lc, t, lam, alam, o);
    if (k0 + 8 <= Lout) {
        *reinterpret_cast<float4*>(out + k0)     = make_float4(o[0], o[1], o[2], o[3]);
        *reinterpret_cast<float4*>(out + k0 + 4) = make_float4(o[4], o[5], o[6], o[7]);
    } else {
        for (int c = 0; c < 8 && k0 + c < Lout; ++c) out[k0 + c] = o[c];
    }
}

__global__ __launch_bounds__(256)
void fidwt8_kernel(const float* __restrict__ cabase, const float* __restrict__ cdbase,
                   long long str, int Lc, const float* __restrict__ sigbase,
                   long long sstr, float* __restrict__ out,
                   const SelState* __restrict__ sel) {
    int chain = blockIdx.y;
    const float* ca = cabase + (size_t)chain * str;
    const float* cd = cdbase + (size_t)chain * str;
    const float* sig = sigbase + (size_t)chain * sstr;
    float* out_diff = out + (size_t)(2 * chain) * L0C;
    float* out_nn   = out + (size_t)(2 * chain + 1) * L0C;
    int t = blockIdx.x * blockDim.x + threadIdx.x;
    int Lout = 2 * Lc - 14;   // == L0C (mult of 8)
    int k0 = 8 * t;
    if (k0 >= Lout) return;
    float lam = sel[chain].lam, alam = 0.85f * lam;
    float o[8];
    idwt_compute8(ca, cd, Lc, t, lam, alam, o);
    float4 s0 = __ldg(reinterpret_cast<const float4*>(sig + k0));
    float4 s1 = __ldg(reinterpret_cast<const float4*>(sig + k0 + 4));
    *reinterpret_cast<float4*>(out_nn + k0)     = make_float4(o[0], o[1], o[2], o[3]);
    *reinterpret_cast<float4*>(out_nn + k0 + 4) = make_float4(o[4], o[5], o[6], o[7]);
    *reinterpret_cast<float4*>(out_diff + k0) =
        make_float4(s0.x - o[0], s0.y - o[1], s0.z - o[2], s0.w - o[3]);
    *reinterpret_cast<float4*>(out_diff + k0 + 4) =
        make_float4(s1.x - o[4], s1.y - o[5], s1.z - o[6], s1.w - o[7]);
}

// ---------------------------------------------------------------------------
static inline int gridFor(long long n, int per) { return (int)((n + per - 1) / per); }

extern "C" void kernel_launch(void* const* d_in, const int* in_sizes, int n_in,
                              void* d_out, int out_size) {
    const float* x = (const float*)d_in[0];
    float* out = (float*)d_out;

    float* scr = nullptr;
    unsigned int* hist = nullptr;
    unsigned int* done = nullptr;
    SelState* sel = nullptr;
    cudaGetSymbolAddress((void**)&scr, g_scratch);
    cudaGetSymbolAddress((void**)&hist, g_hist);
    cudaGetSymbolAddress((void**)&done, g_done);
    cudaGetSymbolAddress((void**)&sel, g_sel);

    float* trend = scr;                     // sig stride = L0C
    float* ch = scr + (size_t)2 * L0C;      // chain stride = CHAIN
    float* a1 = ch;
    float* d1 = ch + L1P;
    float* a2 = ch + (size_t)2 * L1P;
    float* d2 = a2 + L2P;
    float* a3 = d2 + L2P;
    float* d3 = a3 + L3P;
    float* r2 = d3 + L3P;
    float* r1 = r2 + R2C;

    movavg_kernel<<<gridFor((long long)B_ * MA_NCH * N_, 256), 256>>>(x, trend, scr + L0C);

    // level-1 dwt + pass-0 hist + fused select
    dwt4_hist_kernel<<<dim3(gridFor(L1C, 1024), 2), 256>>>(trend, L0C, L0C, a1, d1, CHAIN, L1C,
                                                           hist, sel, done);

    // K2: level-2 dwt blocks + pass-1 hist blocks (+fused select)
    const int HB = 592;
    int g2 = gridFor(L2C, 1024);
    k2_kernel<<<dim3(g2 + HB, 2), 256>>>(a1, a2, d2, d1, hist, sel, done, g2);

    // K3: level-3 dwt blocks + pass-2 hist blocks (+fused select)
    int g3 = gridFor(L3C, 1024);
    k3_kernel<<<dim3(g3 + HB, 2), 256>>>(a2, a3, d3, d1, hist, sel, done, g3);

    // reconstruction with fused thresholding
    idwt8_kernel<<<dim3(gridFor(R2C, 2048), 2), 256>>>(a3, d3, CHAIN, L3C, r2, CHAIN, sel);
    idwt8_kernel<<<dim3(gridFor(R1C, 2048), 2), 256>>>(r2, d2, CHAIN, L2C, r1, CHAIN, sel);
    fidwt8_kernel<<<dim3(gridFor(L0C, 2048), 2), 256>>>(r1, d1, CHAIN, L1C, trend, L0C, out, sel);

    (void)in_sizes; (void)n_in; (void)out_size;
}